// round 14
// baseline (speedup 1.0000x reference)
#include <cuda_runtime.h>
#include <math.h>
#include <stdint.h>
#include <cuda_fp16.h>

#define KCODES 512
#define DIM 64
#define NROWS 262144
#define ROWSB 64
#define NBLK (NROWS / ROWSB)      // 4096
#define TPB 256
#define DSTR 544                  // dist row stride (halves)
#define WCH 68                    // words per code in W tile
#define WBUF (64 * WCH)           // 4352 words per chunk buffer
#define THRESH_BITS 256           // gap threshold in biased-key units (~2.4e-4 min)
#define KEY_BIAS 0x41780000       // bits(15.5)

// smem carve (bytes)
#define OFF_DIST 0
#define SZ_DIST (ROWSB * DSTR * 2)          // 69632
#define OFF_W    (OFF_DIST + SZ_DIST)
#define SZ_W     (2 * WBUF * 4)             // 34816
#define OFF_SW   (OFF_W + SZ_W)
#define OFF_RED  (OFF_SW + 2048)
#define OFF_IDX  (OFF_RED + 2048)
#define OFF_LIST (OFF_IDX + 256)
#define OFF_CNT  (OFF_LIST + 256)
#define DYN_SMEM (OFF_CNT + 16)             // 109088

__device__ float  g_sw[KCODES];
__device__ int    g_counts[KCODES];
__device__ double g_partial[NBLK];
__device__ int    g_done;

__device__ __forceinline__ uint32_t smem_u32(const void* p) {
    uint32_t a;
    asm("{ .reg .u64 t; cvta.to.shared.u64 t, %1; cvt.u32.u64 %0, t; }" : "=r"(a) : "l"(p));
    return a;
}
__device__ __forceinline__ uint32_t to_tf32(float f) {
    uint32_t r;
    asm("cvt.rna.tf32.f32 %0, %1;" : "=r"(r) : "f"(f));
    return r;
}
__device__ __forceinline__ void mma1688(float* c, const uint32_t* a,
                                        uint32_t b0, uint32_t b1) {
    asm volatile("mma.sync.aligned.m16n8k8.row.col.f32.tf32.tf32.f32 "
                 "{%0,%1,%2,%3}, {%4,%5,%6,%7}, {%8,%9}, {%0,%1,%2,%3};"
                 : "+f"(c[0]), "+f"(c[1]), "+f"(c[2]), "+f"(c[3])
                 : "r"(a[0]), "r"(a[1]), "r"(a[2]), "r"(a[3]), "r"(b0), "r"(b1));
}
__device__ __forceinline__ void cpasync16(uint32_t saddr, const void* g) {
    asm volatile("cp.async.cg.shared.global [%0], [%1], 16;" :: "r"(saddr), "l"(g) : "memory");
}
__device__ __forceinline__ int mkkey(float r, int k) {
    float v = fminf(fmaxf(r, -0.49f), 0.49f) + 16.0f;   // r bounded: |2*x.w| <= 0.41
    return ((__float_as_int(v) - KEY_BIAS) << 10) | k;
}

// ---------------------------------------------------------------------------
// Kernel 1: code norms (exact R2 association)
// ---------------------------------------------------------------------------
__global__ void vq_prep(const float* __restrict__ W) {
    int k = blockIdx.x * 64 + threadIdx.x;   // 8 x 64
    const float4* w = (const float4*)(W + (size_t)k * DIM);
    float s = 0.0f;
    #pragma unroll
    for (int g = 0; g < 16; ++g) {
        float4 v = w[g];
        s += v.x * v.x; s += v.y * v.y; s += v.z * v.z; s += v.w * v.w;
    }
    g_sw[k] = s;
}

// ---------------------------------------------------------------------------
// Kernel 2: TF32 MMA scoring -> fp16 dist -> key-scan -> exact fallback ->
//           outputs -> last-CTA finalize.
// Output: out[0]=loss | out[1..1+N*64)=q_st | out[1+N*64]=perp | idx (float)
// ---------------------------------------------------------------------------
extern "C" __global__ void __launch_bounds__(TPB, 2)
vq_main(const float* __restrict__ X, const float* __restrict__ W,
        float* __restrict__ out) {
    extern __shared__ char dynsm[];
    __half* s_dist = (__half*)(dynsm + OFF_DIST);   // [64][544]
    float*  s_w    = (float*)(dynsm + OFF_W);       // 2 x [64][68]
    float*  s_sw   = (float*)(dynsm + OFF_SW);      // [512]
    double* s_red  = (double*)(dynsm + OFF_RED);    // [256]
    int*    s_idx  = (int*)(dynsm + OFF_IDX);       // [64]
    int*    s_list = (int*)(dynsm + OFF_LIST);      // [64]
    int*    s_cnt  = (int*)(dynsm + OFF_CNT);

    const int tid  = threadIdx.x;
    const int lane = tid & 31;
    const int warp = tid >> 5;
    const int g    = lane >> 2;
    const int tl   = lane & 3;
    const int rg   = warp & 3;        // row group (16 rows)
    const int oh   = warp >> 2;       // octet half (codes +0 / +32 within chunk)
    const int rowBase = blockIdx.x * ROWSB;

    if (tid == 0) *s_cnt = 0;
    for (int i = tid; i < KCODES; i += TPB) s_sw[i] = g_sw[i];
    // dist pad [512..544) = large (clamped to 0.49 in scan -> never wins)
    for (int i = tid; i < ROWSB * 16; i += TPB) {
        int r = i >> 4, j = i & 15;
        ((uint32_t*)(s_dist + (size_t)r * DSTR + 512))[j] = 0x7C007C00u;  // +inf halves
    }

    const uint32_t swb = smem_u32(s_w);

    // prefetch W chunk 0 (64 codes x 64 f32)
    {
        const float4* src = (const float4*)W;
        for (int i = tid; i < 1024; i += TPB) {
            int code = i >> 4, d4 = i & 15;
            cpasync16(swb + (uint32_t)(code * WCH + d4 * 4) * 4, src + i);
        }
        asm volatile("cp.async.commit_group;" ::: "memory");
    }

    // A fragments: rows 16*rg + {g, g+8}, tf32-rna (validated in R7)
    uint32_t ah[8][4];
    {
        const float* xr0 = X + (size_t)(rowBase + 16 * rg + g) * DIM;
        const float* xr8 = xr0 + 8 * DIM;
        #pragma unroll
        for (int s = 0; s < 8; ++s) {
            ah[s][0] = to_tf32(xr0[8 * s + tl]);
            ah[s][1] = to_tf32(xr8[8 * s + tl]);
            ah[s][2] = to_tf32(xr0[8 * s + tl + 4]);
            ah[s][3] = to_tf32(xr8[8 * s + tl + 4]);
        }
    }

    // ---- 8 chunks of 64 codes, double-buffered; B = raw f32 (HW tf32 trunc) ----
    for (int c = 0; c < 8; ++c) {
        const int buf = c & 1;
        asm volatile("cp.async.wait_group 0;" ::: "memory");
        __syncthreads();
        if (c < 7) {
            const float4* src = (const float4*)(W + (size_t)(c + 1) * 64 * DIM);
            uint32_t dstb = swb + (uint32_t)((buf ^ 1) * WBUF) * 4;
            for (int i = tid; i < 1024; i += TPB) {
                int code = i >> 4, d4 = i & 15;
                cpasync16(dstb + (uint32_t)(code * WCH + d4 * 4) * 4, src + i);
            }
            asm volatile("cp.async.commit_group;" ::: "memory");
        }

        const float* wb = s_w + buf * WBUF;
        float acc[4][4];
        #pragma unroll
        for (int t = 0; t < 4; ++t)
            acc[t][0] = acc[t][1] = acc[t][2] = acc[t][3] = 0.0f;

        #pragma unroll
        for (int s = 0; s < 8; ++s) {
            #pragma unroll
            for (int t = 0; t < 4; ++t) {          // 4 independent acc chains
                const int wo = (32 * oh + 8 * t + g) * WCH + 8 * s + tl;
                uint32_t b0 = __float_as_uint(wb[wo]);
                uint32_t b1 = __float_as_uint(wb[wo + 4]);
                mma1688(acc[t], ah[s], b0, b1);
            }
        }

        // epilogue: r = sw - 2*dot -> fp16 cache
        const int dr = 16 * rg + g;
        #pragma unroll
        for (int t = 0; t < 4; ++t) {
            const int k0 = 64 * c + 32 * oh + 8 * t + 2 * tl;
            float r0 = fmaf(acc[t][0], -2.0f, s_sw[k0]);
            float r1 = fmaf(acc[t][1], -2.0f, s_sw[k0 + 1]);
            float r2 = fmaf(acc[t][2], -2.0f, s_sw[k0]);
            float r3 = fmaf(acc[t][3], -2.0f, s_sw[k0 + 1]);
            *(__half2*)(s_dist + (size_t)dr * DSTR + k0)       = __floats2half2_rn(r0, r1);
            *(__half2*)(s_dist + (size_t)(dr + 8) * DSTR + k0) = __floats2half2_rn(r2, r3);
        }
    }
    __syncthreads();

    // ---- scan: 4 threads/row, 136 codes each; branch-free min/min2 keys ----
    {
        const int row = tid >> 2;
        const int q   = tid & 3;
        const uint4* du = (const uint4*)(s_dist + (size_t)row * DSTR + 136 * q);
        int m1 = 0x7fffffff, m2 = 0x7fffffff;
        #pragma unroll 4
        for (int j = 0; j < 17; ++j) {
            uint4 u = du[j];
            const uint32_t uw[4] = {u.x, u.y, u.z, u.w};
            #pragma unroll
            for (int e = 0; e < 4; ++e) {
                float2 f = __half22float2(*(const __half2*)&uw[e]);
                int kk = 136 * q + 8 * j + 2 * e;
                int k1 = mkkey(f.x, kk);
                int k2 = mkkey(f.y, kk + 1);
                m2 = min(m2, max(k1, m1)); m1 = min(k1, m1);
                m2 = min(m2, max(k2, m1)); m1 = min(k2, m1);
            }
        }
        #pragma unroll
        for (int off = 1; off <= 2; off <<= 1) {
            int o1 = __shfl_xor_sync(0xffffffffu, m1, off);
            int o2 = __shfl_xor_sync(0xffffffffu, m2, off);
            m2 = min(max(m1, o1), min(m2, o2));
            m1 = min(m1, o1);
        }
        if (q == 0) {
            s_idx[row] = m1 & 1023;
            if (((m2 >> 10) - (m1 >> 10)) < THRESH_BITS) {
                int p = atomicAdd(s_cnt, 1);
                s_list[p] = row;
            }
        }
    }
    __syncthreads();

    // ---- ambiguous rows: warp-cooperative exact scan (R2 comparator) ----
    const int namb = *s_cnt;
    for (int i = warp; i < namb; i += 8) {
        const int r = s_list[i];
        const int rowG = rowBase + r;
        float4 x[16];
        const float4* xp = (const float4*)(X + (size_t)rowG * DIM);
        #pragma unroll
        for (int gg = 0; gg < 16; ++gg) x[gg] = xp[gg];
        float sx = 0.0f;
        #pragma unroll
        for (int gg = 0; gg < 16; ++gg) {
            sx += x[gg].x * x[gg].x; sx += x[gg].y * x[gg].y;
            sx += x[gg].z * x[gg].z; sx += x[gg].w * x[gg].w;
        }
        float bd = __int_as_float(0x7f800000);
        int bi = KCODES;
        for (int k = lane; k < KCODES; k += 32) {
            const float4* wp = (const float4*)(W + (size_t)k * DIM);
            float dot = 0.0f;
            #pragma unroll
            for (int gg = 0; gg < 16; ++gg) {
                float4 w4 = __ldg(wp + gg);
                dot += x[gg].x * w4.x; dot += x[gg].y * w4.y;
                dot += x[gg].z * w4.z; dot += x[gg].w * w4.w;
            }
            float tt = sx + s_sw[k];
            float dist = tt - 2.0f * dot;
            if (dist < bd) { bd = dist; bi = k; }
        }
        #pragma unroll
        for (int off = 16; off > 0; off >>= 1) {
            float ob = __shfl_xor_sync(0xffffffffu, bd, off);
            int   oi = __shfl_xor_sync(0xffffffffu, bi, off);
            if (ob < bd || (ob == bd && oi < bi)) { bd = ob; bi = oi; }
        }
        if (lane == 0) s_idx[r] = bi;
    }
    __syncthreads();

    // ---- idx + histogram ----
    if (tid < ROWSB) {
        int bi = s_idx[tid];
        out[2 + (size_t)NROWS * DIM + rowBase + tid] = (float)bi;
        atomicAdd(&g_counts[bi], 1);
    }

    // ---- q_st + loss: 4 threads/row, 16 dims each (4B-aligned -> scalar STG) ----
    double lsum = 0.0;
    {
        const int row  = tid >> 2;
        const int sub  = tid & 3;
        const int rowG = rowBase + row;
        const int kb   = s_idx[row];
        const float4* qp  = (const float4*)(W + (size_t)kb * DIM + sub * 16);
        const float4* xp2 = (const float4*)(X + (size_t)rowG * DIM + sub * 16);
        float* op = out + 1 + (size_t)rowG * DIM + sub * 16;
        #pragma unroll
        for (int gg = 0; gg < 4; ++gg) {
            float4 q4 = __ldg(qp + gg);
            float4 xv = xp2[gg];
            float e;
            e = q4.x - xv.x; op[4*gg + 0] = xv.x + e; lsum += (double)(e * e);
            e = q4.y - xv.y; op[4*gg + 1] = xv.y + e; lsum += (double)(e * e);
            e = q4.z - xv.z; op[4*gg + 2] = xv.z + e; lsum += (double)(e * e);
            e = q4.w - xv.w; op[4*gg + 3] = xv.w + e; lsum += (double)(e * e);
        }
    }
    s_red[tid] = lsum;
    __syncthreads();
    for (int s = TPB / 2; s > 0; s >>= 1) {
        if (tid < s) s_red[tid] += s_red[tid + s];
        __syncthreads();
    }
    if (tid == 0) g_partial[blockIdx.x] = s_red[0];

    // ---- last-CTA finalize ----
    __shared__ int s_last;
    __threadfence();
    if (tid == 0) {
        int d = atomicAdd(&g_done, 1);
        s_last = (d == NBLK - 1);
    }
    __syncthreads();
    if (!s_last) return;
    __threadfence();

    double v = 0.0;
    for (int i = tid; i < NBLK; i += TPB) v += g_partial[i];   // fixed order
    s_red[tid] = v;

    float* s_f = s_sw;                                         // reuse
    float pf = 0.0f;
    #pragma unroll
    for (int h = 0; h < 2; ++h) {
        int k = tid + h * TPB;
        float cc = (float)g_counts[k] / (float)NROWS;
        pf += cc * logf(cc + 1e-10f);
        g_counts[k] = 0;                                       // reset for next launch
    }
    s_f[tid] = pf;
    __syncthreads();
    for (int s = TPB / 2; s > 0; s >>= 1) {
        if (tid < s) { s_red[tid] += s_red[tid + s]; s_f[tid] += s_f[tid + s]; }
        __syncthreads();
    }
    if (tid == 0) {
        float m = (float)(s_red[0] / ((double)NROWS * (double)DIM));
        out[0] = m + 0.25f * m;
        out[1 + (size_t)NROWS * DIM] = expf(-s_f[0]) / (float)KCODES;
        g_done = 0;
    }
}

// ---------------------------------------------------------------------------
extern "C" void kernel_launch(void* const* d_in, const int* in_sizes, int n_in,
                              void* d_out, int out_size) {
    const float* X = (const float*)d_in[0];   // inputs  [N, 64]
    const float* W = (const float*)d_in[1];   // emb_weight [512, 64]
    float* out = (float*)d_out;

    cudaFuncSetAttribute((const void*)vq_main,
                         cudaFuncAttributeMaxDynamicSharedMemorySize, DYN_SMEM);

    vq_prep<<<KCODES / 64, 64>>>(W);
    vq_main<<<NBLK, TPB, DYN_SMEM>>>(X, W, out);
}